// round 5
// baseline (speedup 1.0000x reference)
#include <cuda_runtime.h>
#include <cuda_fp16.h>
#include <cstdint>

// ===================== problem constants =====================
#define DIMD 1024
#define BATCH 65536
#define NITERS 20

// phase-1 config: heterogeneous grid
#define NCTA_S 256          // sinkhorn CTAs (barrier participants)
#define RPC 4               // rows per sinkhorn CTA (256*4 = 1024)
#define NTHR 128
#define CVT_CTAS 2048       // converter CTAs
#define N4 16777216         // BATCH/4 * DIMD float4 elements of emb

// ===================== device globals (static scratch; never allocated) =====================
__device__ __half  g_P[DIMD * DIMD];            // Sinkhorn P (row-major = K-major B operand)
__device__ __half  g_A16[(size_t)BATCH * DIMD]; // fp16 embeddings
__device__ float   g_colSum[NITERS][DIMD];      // per-iter column sums (atomic-accumulated)
__device__ unsigned g_bar;                      // monotonic grid barrier counter
__device__ unsigned g_done;                     // end-of-kernel reset rendezvous

// ===================== small PTX helpers (plain sm_103-legal only) =====================
__device__ __forceinline__ uint32_t smem_to_u32(const void* p) {
    uint32_t a;
    asm("{ .reg .u64 t; cvta.to.shared.u64 t, %1; cvt.u32.u64 %0, t; }" : "=r"(a) : "l"(p));
    return a;
}

#define CP_ASYNC16(dst, src) \
    asm volatile("cp.async.cg.shared.global [%0], [%1], 16;" :: "r"(dst), "l"(src) : "memory")
#define CP_ASYNC_COMMIT() asm volatile("cp.async.commit_group;" ::: "memory")
#define CP_ASYNC_WAIT1()  asm volatile("cp.async.wait_group 1;" ::: "memory")

__device__ __forceinline__ void ldsm_x4(uint32_t* r, uint32_t addr) {
    asm volatile("ldmatrix.sync.aligned.m8n8.x4.shared.b16 {%0,%1,%2,%3}, [%4];"
                 : "=r"(r[0]), "=r"(r[1]), "=r"(r[2]), "=r"(r[3]) : "r"(addr));
}
__device__ __forceinline__ void mma16816(float* d, const uint32_t* a, uint32_t b0, uint32_t b1) {
    asm volatile("mma.sync.aligned.m16n8k16.row.col.f32.f16.f16.f32 "
                 "{%0,%1,%2,%3}, {%4,%5,%6,%7}, {%8,%9}, {%0,%1,%2,%3};"
                 : "+f"(d[0]), "+f"(d[1]), "+f"(d[2]), "+f"(d[3])
                 : "r"(a[0]), "r"(a[1]), "r"(a[2]), "r"(a[3]), "r"(b0), "r"(b1));
}

// ===================== phase 1: sinkhorn (256 CTAs) + concurrent cvt (2048 CTAs) =====================
__device__ __forceinline__ void grid_barrier_s(unsigned* tgt) {
    __syncthreads();
    if (threadIdx.x == 0) {
        __threadfence();
        atomicAdd(&g_bar, 1u);
        const unsigned t = *tgt;
        while (*((const volatile unsigned*)&g_bar) < t) { __nanosleep(64); }
        __threadfence();
    }
    __syncthreads();
    *tgt += NCTA_S;
}

__global__ void __launch_bounds__(NTHR)
phase1_kernel(const float* __restrict__ log_scores, const float4* __restrict__ emb) {
    // ---------------- converter role ----------------
    if (blockIdx.x >= NCTA_S) {
        const int cvt_id = blockIdx.x - NCTA_S;
        uint2* dst = reinterpret_cast<uint2*>(g_A16);
        for (int i = cvt_id * NTHR + threadIdx.x; i < N4; i += CVT_CTAS * NTHR) {
            const float4 v = emb[i];
            __half2 h0 = __floats2half2_rn(v.x, v.y);
            __half2 h1 = __floats2half2_rn(v.z, v.w);
            dst[i] = make_uint2(*reinterpret_cast<const uint32_t*>(&h0),
                                *reinterpret_cast<const uint32_t*>(&h1));
        }
        return;
    }

    // ---------------- sinkhorn role ----------------
    __shared__ float rows[RPC][DIMD];   // 16 KB
    __shared__ float cs_s[DIMD];        // 4 KB
    const int tid  = threadIdx.x;
    const int warp = tid >> 5;          // 4 warps = 4 rows
    const int lane = tid & 31;
    const int cta  = blockIdx.x;
    const int rbase = cta * RPC;

    // zero colSum buffers (visibility covered by barrier 0)
    for (int i = cta * NTHR + tid; i < NITERS * DIMD; i += NCTA_S * NTHR)
        (&g_colSum[0][0])[i] = 0.f;

    // load rows, go to probability domain (TAU = 1)
    for (int i = tid; i < RPC * DIMD; i += NTHR)
        rows[i >> 10][i & 1023] = __expf(log_scores[(size_t)rbase * DIMD + i]);

    unsigned tgt = NCTA_S;
    grid_barrier_s(&tgt);

    for (int iter = 0; iter < NITERS; ++iter) {
        if (iter > 0) {
            #pragma unroll
            for (int c = tid; c < DIMD; c += NTHR)
                cs_s[c] = __frcp_rn(g_colSum[iter - 1][c]);
            __syncthreads();
        }

        // row normalize: warp w owns row w (fold pending column division)
        {
            float v[32];
            float s = 0.f;
            #pragma unroll
            for (int j = 0; j < 32; ++j) {
                const int col = lane + j * 32;
                float x = rows[warp][col];
                if (iter > 0) x *= cs_s[col];
                v[j] = x;
                s += x;
            }
            #pragma unroll
            for (int o = 16; o; o >>= 1) s += __shfl_xor_sync(0xFFFFFFFFu, s, o);
            const float inv = __frcp_rn(s);
            #pragma unroll
            for (int j = 0; j < 32; ++j) rows[warp][lane + j * 32] = v[j] * inv;
        }
        __syncthreads();

        // column partial over this CTA's 4 rows -> one atomic per column
        #pragma unroll
        for (int c = 0; c < DIMD / NTHR; ++c) {
            const int col = tid + c * NTHR;
            float p = 0.f;
            #pragma unroll
            for (int r = 0; r < RPC; ++r) p += rows[r][col];
            atomicAdd(&g_colSum[iter][col], p);
        }

        grid_barrier_s(&tgt);
    }

    // final: apply last column normalization, emit P as fp16 (K-major B operand)
    #pragma unroll
    for (int c = tid; c < DIMD; c += NTHR)
        cs_s[c] = __frcp_rn(g_colSum[NITERS - 1][c]);
    __syncthreads();
    for (int i = tid; i < RPC * DIMD; i += NTHR) {
        const int r = i >> 10, col = i & 1023;
        g_P[(size_t)(rbase + r) * DIMD + col] = __float2half(rows[r][col] * cs_s[col]);
    }

    // reset barrier counters for the next graph replay (sinkhorn CTAs only)
    __syncthreads();
    if (tid == 0) {
        __threadfence();
        atomicAdd(&g_done, 1u);
        if (blockIdx.x == 0) {
            while (*((const volatile unsigned*)&g_done) < NCTA_S) { }
            g_bar = 0u;
            g_done = 0u;
            __threadfence();
        }
    }
}

// ===================== GEMM: out = A16 @ P^T =====================
// CTA tile 128x128, 4 warps (2x2), warp tile 64x64, K-stage 64 (16 stages), 3-stage cp.async.
// smem: 3 x (A 16KB + B 16KB) = 96KB. Swizzle: row*128 + (kByte ^ ((row&7)<<4)).
#define KSTAGES 16
#define STAGE_BYTES 16384
#define B_BASE (3 * STAGE_BYTES)
#define GSMEM_BYTES (6 * STAGE_BYTES)

__global__ void __launch_bounds__(128, 2)
gemm_kernel(float* __restrict__ out) {
    extern __shared__ __align__(1024) char smem[];
    const uint32_t sb = smem_to_u32(smem);
    const int tid  = threadIdx.x;
    const int wid  = tid >> 5;
    const int lane = tid & 31;

    // ntile fast-moving -> 8 consecutive CTAs share one A row-block (L2 reuse of A)
    const int ntile = blockIdx.x & 7;
    const int mtile = blockIdx.x >> 3;
    const int m0 = mtile * 128;
    const int n0 = ntile * 128;

    const __half* Ag = g_A16 + (size_t)m0 * DIMD;
    const __half* Bg = g_P   + (size_t)n0 * DIMD;

#define ISSUE_STAGE(st, buf)                                                     \
    {                                                                            \
        const __half* asrc = Ag + (st) * 64;                                     \
        const __half* bsrc = Bg + (st) * 64;                                     \
        const uint32_t abase = sb + (buf) * STAGE_BYTES;                         \
        const uint32_t bbase = sb + B_BASE + (buf) * STAGE_BYTES;                \
        _Pragma("unroll")                                                        \
        for (int i = 0; i < 8; ++i) {                                            \
            const int idx = tid + i * 128;                                       \
            const int r = idx >> 3, c = idx & 7;                                 \
            const uint32_t sw = (uint32_t)(r * 128 + ((c * 16) ^ ((r & 7) << 4)));\
            CP_ASYNC16(abase + sw, asrc + (size_t)r * DIMD + c * 8);             \
            CP_ASYNC16(bbase + sw, bsrc + (size_t)r * DIMD + c * 8);             \
        }                                                                        \
        CP_ASYNC_COMMIT();                                                       \
    }

    const int warp_m = wid >> 1;   // 0..1
    const int warp_n = wid & 1;    // 0..1

    // A fragment addresses: 4 m16 tiles per warp (64 rows)
    int a_pre[4], a_sw[4];
    {
        const int rr = ((lane >> 3) & 1) * 8 + (lane & 7);
        #pragma unroll
        for (int mt = 0; mt < 4; ++mt) {
            const int row = warp_m * 64 + mt * 16 + rr;
            a_pre[mt] = row * 128;
            a_sw[mt]  = (row & 7) << 4;
        }
    }
    const int a_k16 = ((lane >> 4) & 1) * 16;

    // B fragment addresses: 4 n16 pairs per warp (64 cols)
    int b_pre[4], b_sw[4];
    {
        const int rr = ((lane >> 4) & 1) * 8 + (lane & 7);
        #pragma unroll
        for (int np = 0; np < 4; ++np) {
            const int row = warp_n * 64 + np * 16 + rr;
            b_pre[np] = row * 128;
            b_sw[np]  = (row & 7) << 4;
        }
    }
    const int b_k16 = ((lane >> 3) & 1) * 16;

    float acc[4][8][4];
    #pragma unroll
    for (int mt = 0; mt < 4; ++mt)
        #pragma unroll
        for (int nt = 0; nt < 8; ++nt)
            #pragma unroll
            for (int j = 0; j < 4; ++j) acc[mt][nt][j] = 0.f;

    ISSUE_STAGE(0, 0);
    ISSUE_STAGE(1, 1);

    for (int s = 0; s < KSTAGES; ++s) {
        const int buf = s % 3;
        CP_ASYNC_WAIT1();
        __syncthreads();
        if (s + 2 < KSTAGES) { ISSUE_STAGE(s + 2, (s + 2) % 3); }
        else                 { CP_ASYNC_COMMIT(); }

        const uint32_t Ab = sb + buf * STAGE_BYTES;
        const uint32_t Bb = sb + B_BASE + buf * STAGE_BYTES;
        #pragma unroll
        for (int ks = 0; ks < 4; ++ks) {
            const int kb = ks * 32;
            uint32_t av[4][4];
            #pragma unroll
            for (int mt = 0; mt < 4; ++mt)
                ldsm_x4(av[mt], Ab + a_pre[mt] + ((kb | a_k16) ^ a_sw[mt]));
            uint32_t bv[4][4];
            #pragma unroll
            for (int np = 0; np < 4; ++np)
                ldsm_x4(bv[np], Bb + b_pre[np] + ((kb | b_k16) ^ b_sw[np]));
            #pragma unroll
            for (int mt = 0; mt < 4; ++mt)
                #pragma unroll
                for (int np = 0; np < 4; ++np) {
                    mma16816(acc[mt][2 * np + 0], av[mt], bv[np][0], bv[np][1]);
                    mma16816(acc[mt][2 * np + 1], av[mt], bv[np][2], bv[np][3]);
                }
        }
    }
#undef ISSUE_STAGE

    // epilogue: direct coalesced STG.64
    const int r0c = lane >> 2;
    const int c0c = (lane & 3) * 2;
    #pragma unroll
    for (int mt = 0; mt < 4; ++mt) {
        const int row_base = m0 + warp_m * 64 + mt * 16 + r0c;
        #pragma unroll
        for (int nt = 0; nt < 8; ++nt) {
            const int col = n0 + warp_n * 64 + nt * 8 + c0c;
            float2 v0 = make_float2(acc[mt][nt][0], acc[mt][nt][1]);
            float2 v1 = make_float2(acc[mt][nt][2], acc[mt][nt][3]);
            *reinterpret_cast<float2*>(out + (size_t)row_base * DIMD + col)       = v0;
            *reinterpret_cast<float2*>(out + (size_t)(row_base + 8) * DIMD + col) = v1;
        }
    }
}

// ===================== launch =====================
extern "C" void kernel_launch(void* const* d_in, const int* in_sizes, int n_in,
                              void* d_out, int out_size) {
    const float* emb;
    const float* ls;
    if (n_in >= 2 && in_sizes[0] == DIMD * DIMD && in_sizes[1] != DIMD * DIMD) {
        ls  = (const float*)d_in[0];
        emb = (const float*)d_in[1];
    } else {
        emb = (const float*)d_in[0];
        ls  = (const float*)d_in[1];
    }
    float* out = (float*)d_out;

    static bool attr_done = false;
    if (!attr_done) {
        cudaFuncSetAttribute(gemm_kernel, cudaFuncAttributeMaxDynamicSharedMemorySize, GSMEM_BYTES);
        attr_done = true;
    }

    phase1_kernel<<<NCTA_S + CVT_CTAS, NTHR>>>(ls, reinterpret_cast<const float4*>(emb));
    gemm_kernel<<<(BATCH / 128) * (DIMD / 128), 128, GSMEM_BYTES>>>(out);
}

// round 6
// speedup vs baseline: 1.0075x; 1.0075x over previous
#include <cuda_runtime.h>
#include <cuda_fp16.h>
#include <cstdint>

// ===================== problem constants =====================
#define DIMD 1024
#define BATCH 65536
#define NITERS 20

// sinkhorn config
#define NCTA_S 128
#define STHR 256
#define RPC 8               // rows per sinkhorn CTA (128*8 = 1024)

#define NMTILES 512         // BATCH/128

// ===================== device globals (static scratch; never allocated) =====================
__device__ __half  g_P[DIMD * DIMD];            // Sinkhorn P (row-major = K-major B operand)
__device__ __half  g_A16[(size_t)BATCH * DIMD]; // fp16 embeddings (converted in GEMM prologue)
__device__ float   g_colSum[NITERS][DIMD];      // per-iter column sums (atomic-accumulated)
__device__ unsigned g_bar;                      // monotonic grid barrier counter
__device__ unsigned g_done;                     // end-of-kernel reset rendezvous
__device__ unsigned g_mtileCnt[NMTILES];        // A-convert arrival counters (zeroed by sinkhorn)

// ===================== small PTX helpers (plain sm_103-legal only) =====================
__device__ __forceinline__ uint32_t smem_to_u32(const void* p) {
    uint32_t a;
    asm("{ .reg .u64 t; cvta.to.shared.u64 t, %1; cvt.u32.u64 %0, t; }" : "=r"(a) : "l"(p));
    return a;
}

#define CP_ASYNC16(dst, src) \
    asm volatile("cp.async.cg.shared.global [%0], [%1], 16;" :: "r"(dst), "l"(src) : "memory")
#define CP_ASYNC_COMMIT() asm volatile("cp.async.commit_group;" ::: "memory")
#define CP_ASYNC_WAIT1()  asm volatile("cp.async.wait_group 1;" ::: "memory")

__device__ __forceinline__ void ldsm_x4(uint32_t* r, uint32_t addr) {
    asm volatile("ldmatrix.sync.aligned.m8n8.x4.shared.b16 {%0,%1,%2,%3}, [%4];"
                 : "=r"(r[0]), "=r"(r[1]), "=r"(r[2]), "=r"(r[3]) : "r"(addr));
}
__device__ __forceinline__ void mma16816(float* d, const uint32_t* a, uint32_t b0, uint32_t b1) {
    asm volatile("mma.sync.aligned.m16n8k16.row.col.f32.f16.f16.f32 "
                 "{%0,%1,%2,%3}, {%4,%5,%6,%7}, {%8,%9}, {%0,%1,%2,%3};"
                 : "+f"(d[0]), "+f"(d[1]), "+f"(d[2]), "+f"(d[3])
                 : "r"(a[0]), "r"(a[1]), "r"(a[2]), "r"(a[3]), "r"(b0), "r"(b1));
}

// ===================== phase 1: pure Sinkhorn (128 CTAs x 256 thr) =====================
__device__ __forceinline__ void grid_barrier_s(unsigned* tgt) {
    __syncthreads();
    if (threadIdx.x == 0) {
        __threadfence();
        atomicAdd(&g_bar, 1u);
        const unsigned t = *tgt;
        while (*((const volatile unsigned*)&g_bar) < t) { __nanosleep(32); }
        __threadfence();
    }
    __syncthreads();
    *tgt += NCTA_S;
}

__global__ void __launch_bounds__(STHR)
sinkhorn_kernel(const float* __restrict__ log_scores) {
    __shared__ float rows[RPC][DIMD];   // 32 KB
    __shared__ float cs_s[DIMD];        // 4 KB
    const int tid  = threadIdx.x;
    const int warp = tid >> 5;          // 8 warps = 8 rows
    const int lane = tid & 31;
    const int cta  = blockIdx.x;
    const int rbase = cta * RPC;

    // zero colSum + mtile counters (visibility covered by barrier 0)
    for (int i = cta * STHR + tid; i < NITERS * DIMD; i += NCTA_S * STHR)
        (&g_colSum[0][0])[i] = 0.f;
    for (int i = cta * STHR + tid; i < NMTILES; i += NCTA_S * STHR)
        g_mtileCnt[i] = 0u;

    // load rows, go to probability domain (TAU = 1)
    for (int i = tid; i < RPC * DIMD; i += STHR)
        rows[i >> 10][i & 1023] = __expf(log_scores[(size_t)rbase * DIMD + i]);

    unsigned tgt = NCTA_S;
    grid_barrier_s(&tgt);

    for (int iter = 0; iter < NITERS; ++iter) {
        if (iter > 0) {
            #pragma unroll
            for (int c = tid; c < DIMD; c += STHR)
                cs_s[c] = __frcp_rn(g_colSum[iter - 1][c]);
            __syncthreads();
        }

        // row normalize: warp w owns row w (fold pending column division)
        {
            float v[32];
            float s = 0.f;
            #pragma unroll
            for (int j = 0; j < 32; ++j) {
                const int col = lane + j * 32;
                float x = rows[warp][col];
                if (iter > 0) x *= cs_s[col];
                v[j] = x;
                s += x;
            }
            #pragma unroll
            for (int o = 16; o; o >>= 1) s += __shfl_xor_sync(0xFFFFFFFFu, s, o);
            const float inv = __frcp_rn(s);
            #pragma unroll
            for (int j = 0; j < 32; ++j) rows[warp][lane + j * 32] = v[j] * inv;
        }
        __syncthreads();

        // column partial over this CTA's 8 rows -> one atomic per column
        #pragma unroll
        for (int c = 0; c < DIMD / STHR; ++c) {
            const int col = tid + c * STHR;
            float p = 0.f;
            #pragma unroll
            for (int r = 0; r < RPC; ++r) p += rows[r][col];
            atomicAdd(&g_colSum[iter][col], p);
        }

        grid_barrier_s(&tgt);
    }

    // final: apply last column normalization, emit P as fp16 (K-major B operand)
    #pragma unroll
    for (int c = tid; c < DIMD; c += STHR)
        cs_s[c] = __frcp_rn(g_colSum[NITERS - 1][c]);
    __syncthreads();
    for (int i = tid; i < RPC * DIMD; i += STHR) {
        const int r = i >> 10, col = i & 1023;
        g_P[(size_t)(rbase + r) * DIMD + col] = __float2half(rows[r][col] * cs_s[col]);
    }

    // reset barrier counters for the next graph replay
    __syncthreads();
    if (tid == 0) {
        __threadfence();
        atomicAdd(&g_done, 1u);
        if (blockIdx.x == 0) {
            while (*((const volatile unsigned*)&g_done) < NCTA_S) { }
            g_bar = 0u;
            g_done = 0u;
            __threadfence();
        }
    }
}

// ===================== GEMM: out = A16 @ P^T, with fused A-convert prologue =====================
// CTA tile 128x128, 4 warps (2x2), warp tile 64x64, K-stage 64 (16 stages), 3-stage cp.async.
// Prologue: the 8 CTAs of one mtile group cooperatively convert the group's
// 128x1024 fp32 A slice to fp16 (16 rows each), then rendezvous on g_mtileCnt.
#define KSTAGES 16
#define STAGE_BYTES 16384
#define B_BASE (3 * STAGE_BYTES)
#define GSMEM_BYTES (6 * STAGE_BYTES)

__global__ void __launch_bounds__(128, 2)
gemm_kernel(const float4* __restrict__ embF, float* __restrict__ out) {
    extern __shared__ __align__(1024) char smem[];
    const uint32_t sb = smem_to_u32(smem);
    const int tid  = threadIdx.x;
    const int wid  = tid >> 5;
    const int lane = tid & 31;

    // ntile fast-moving -> 8 consecutive CTAs share one A row-block (L2 reuse of A)
    const int ntile = blockIdx.x & 7;
    const int mtile = blockIdx.x >> 3;
    const int m0 = mtile * 128;
    const int n0 = ntile * 128;

    // ---- A-convert prologue: this CTA converts rows [m0 + ntile*16, +16) ----
    {
        const size_t base4 = ((size_t)(m0 + ntile * 16) * DIMD) >> 2;  // float4 index
        const float4* src = embF + base4;
        uint2* dst = reinterpret_cast<uint2*>(g_A16) + base4;
        #pragma unroll 4
        for (int i = tid; i < 16 * DIMD / 4; i += 128) {
            const float4 v = src[i];
            __half2 h0 = __floats2half2_rn(v.x, v.y);
            __half2 h1 = __floats2half2_rn(v.z, v.w);
            dst[i] = make_uint2(*reinterpret_cast<const uint32_t*>(&h0),
                                *reinterpret_cast<const uint32_t*>(&h1));
        }
        __threadfence();
        __syncthreads();
        if (tid == 0) {
            atomicAdd(&g_mtileCnt[mtile], 1u);
            while (*((const volatile unsigned*)&g_mtileCnt[mtile]) < 8u) { __nanosleep(32); }
            __threadfence();
        }
        __syncthreads();
    }

    const __half* Ag = g_A16 + (size_t)m0 * DIMD;
    const __half* Bg = g_P   + (size_t)n0 * DIMD;

#define ISSUE_STAGE(st, buf)                                                     \
    {                                                                            \
        const __half* asrc = Ag + (st) * 64;                                     \
        const __half* bsrc = Bg + (st) * 64;                                     \
        const uint32_t abase = sb + (buf) * STAGE_BYTES;                         \
        const uint32_t bbase = sb + B_BASE + (buf) * STAGE_BYTES;                \
        _Pragma("unroll")                                                        \
        for (int i = 0; i < 8; ++i) {                                            \
            const int idx = tid + i * 128;                                       \
            const int r = idx >> 3, c = idx & 7;                                 \
            const uint32_t sw = (uint32_t)(r * 128 + ((c * 16) ^ ((r & 7) << 4)));\
            CP_ASYNC16(abase + sw, asrc + (size_t)r * DIMD + c * 8);             \
            CP_ASYNC16(bbase + sw, bsrc + (size_t)r * DIMD + c * 8);             \
        }                                                                        \
        CP_ASYNC_COMMIT();                                                       \
    }

    const int warp_m = wid >> 1;   // 0..1
    const int warp_n = wid & 1;    // 0..1

    int a_pre[4], a_sw[4];
    {
        const int rr = ((lane >> 3) & 1) * 8 + (lane & 7);
        #pragma unroll
        for (int mt = 0; mt < 4; ++mt) {
            const int row = warp_m * 64 + mt * 16 + rr;
            a_pre[mt] = row * 128;
            a_sw[mt]  = (row & 7) << 4;
        }
    }
    const int a_k16 = ((lane >> 4) & 1) * 16;

    int b_pre[4], b_sw[4];
    {
        const int rr = ((lane >> 4) & 1) * 8 + (lane & 7);
        #pragma unroll
        for (int np = 0; np < 4; ++np) {
            const int row = warp_n * 64 + np * 16 + rr;
            b_pre[np] = row * 128;
            b_sw[np]  = (row & 7) << 4;
        }
    }
    const int b_k16 = ((lane >> 3) & 1) * 16;

    float acc[4][8][4];
    #pragma unroll
    for (int mt = 0; mt < 4; ++mt)
        #pragma unroll
        for (int nt = 0; nt < 8; ++nt)
            #pragma unroll
            for (int j = 0; j < 4; ++j) acc[mt][nt][j] = 0.f;

    ISSUE_STAGE(0, 0);
    ISSUE_STAGE(1, 1);

    for (int s = 0; s < KSTAGES; ++s) {
        const int buf = s % 3;
        CP_ASYNC_WAIT1();
        __syncthreads();
        if (s + 2 < KSTAGES) { ISSUE_STAGE(s + 2, (s + 2) % 3); }
        else                 { CP_ASYNC_COMMIT(); }

        const uint32_t Ab = sb + buf * STAGE_BYTES;
        const uint32_t Bb = sb + B_BASE + buf * STAGE_BYTES;
        #pragma unroll
        for (int ks = 0; ks < 4; ++ks) {
            const int kb = ks * 32;
            uint32_t av[4][4];
            #pragma unroll
            for (int mt = 0; mt < 4; ++mt)
                ldsm_x4(av[mt], Ab + a_pre[mt] + ((kb | a_k16) ^ a_sw[mt]));
            uint32_t bv[4][4];
            #pragma unroll
            for (int np = 0; np < 4; ++np)
                ldsm_x4(bv[np], Bb + b_pre[np] + ((kb | b_k16) ^ b_sw[np]));
            #pragma unroll
            for (int mt = 0; mt < 4; ++mt)
                #pragma unroll
                for (int np = 0; np < 4; ++np) {
                    mma16816(acc[mt][2 * np + 0], av[mt], bv[np][0], bv[np][1]);
                    mma16816(acc[mt][2 * np + 1], av[mt], bv[np][2], bv[np][3]);
                }
        }
    }
#undef ISSUE_STAGE

    // epilogue: direct coalesced STG.64
    const int r0c = lane >> 2;
    const int c0c = (lane & 3) * 2;
    #pragma unroll
    for (int mt = 0; mt < 4; ++mt) {
        const int row_base = m0 + warp_m * 64 + mt * 16 + r0c;
        #pragma unroll
        for (int nt = 0; nt < 8; ++nt) {
            const int col = n0 + warp_n * 64 + nt * 8 + c0c;
            float2 v0 = make_float2(acc[mt][nt][0], acc[mt][nt][1]);
            float2 v1 = make_float2(acc[mt][nt][2], acc[mt][nt][3]);
            *reinterpret_cast<float2*>(out + (size_t)row_base * DIMD + col)       = v0;
            *reinterpret_cast<float2*>(out + (size_t)(row_base + 8) * DIMD + col) = v1;
        }
    }
}

// ===================== launch =====================
extern "C" void kernel_launch(void* const* d_in, const int* in_sizes, int n_in,
                              void* d_out, int out_size) {
    const float* emb;
    const float* ls;
    if (n_in >= 2 && in_sizes[0] == DIMD * DIMD && in_sizes[1] != DIMD * DIMD) {
        ls  = (const float*)d_in[0];
        emb = (const float*)d_in[1];
    } else {
        emb = (const float*)d_in[0];
        ls  = (const float*)d_in[1];
    }
    float* out = (float*)d_out;

    static bool attr_done = false;
    if (!attr_done) {
        cudaFuncSetAttribute(gemm_kernel, cudaFuncAttributeMaxDynamicSharedMemorySize, GSMEM_BYTES);
        attr_done = true;
    }

    sinkhorn_kernel<<<NCTA_S, STHR>>>(ls);
    gemm_kernel<<<(BATCH / 128) * (DIMD / 128), 128, GSMEM_BYTES>>>(
        reinterpret_cast<const float4*>(emb), out);
}

// round 7
// speedup vs baseline: 1.0403x; 1.0326x over previous
#include <cuda_runtime.h>
#include <cuda_fp16.h>
#include <cstdint>

// ===================== problem constants =====================
#define DIMD 1024
#define BATCH 65536
#define NITERS 20

// sinkhorn config
#define NCTA_S 128
#define STHR 256
#define RPC 8               // rows per sinkhorn CTA (128*8 = 1024)

#define NSLICES 4096        // 16-row conversion slices (BATCH/16)
#define CVT_CTAS 1024

// ===================== device globals (static scratch; never allocated) =====================
__device__ __half  g_P[DIMD * DIMD];            // Sinkhorn P (row-major = K-major B operand)
__device__ __half  g_A16[(size_t)BATCH * DIMD]; // fp16 embeddings
__device__ float   g_colSum[NITERS][DIMD];      // per-iter column sums (atomic-accumulated)
__device__ unsigned g_bar;                      // monotonic grid barrier counter
__device__ unsigned g_done;                     // end-of-kernel reset rendezvous
__device__ unsigned g_claim[NSLICES];           // slice conversion claims
__device__ unsigned g_ready[NSLICES];           // slice conversion done flags

// ===================== small PTX helpers (plain sm_103-legal only) =====================
__device__ __forceinline__ uint32_t smem_to_u32(const void* p) {
    uint32_t a;
    asm("{ .reg .u64 t; cvta.to.shared.u64 t, %1; cvt.u32.u64 %0, t; }" : "=r"(a) : "l"(p));
    return a;
}

#define CP_ASYNC16(dst, src) \
    asm volatile("cp.async.cg.shared.global [%0], [%1], 16;" :: "r"(dst), "l"(src) : "memory")
#define CP_ASYNC_COMMIT() asm volatile("cp.async.commit_group;" ::: "memory")
#define CP_ASYNC_WAIT1()  asm volatile("cp.async.wait_group 1;" ::: "memory")

__device__ __forceinline__ void ldsm_x4(uint32_t* r, uint32_t addr) {
    asm volatile("ldmatrix.sync.aligned.m8n8.x4.shared.b16 {%0,%1,%2,%3}, [%4];"
                 : "=r"(r[0]), "=r"(r[1]), "=r"(r[2]), "=r"(r[3]) : "r"(addr));
}
__device__ __forceinline__ void mma16816(float* d, const uint32_t* a, uint32_t b0, uint32_t b1) {
    asm volatile("mma.sync.aligned.m16n8k16.row.col.f32.f16.f16.f32 "
                 "{%0,%1,%2,%3}, {%4,%5,%6,%7}, {%8,%9}, {%0,%1,%2,%3};"
                 : "+f"(d[0]), "+f"(d[1]), "+f"(d[2]), "+f"(d[3])
                 : "r"(a[0]), "r"(a[1]), "r"(a[2]), "r"(a[3]), "r"(b0), "r"(b1));
}

// slice converter: rows [s*16, s*16+16) of emb -> g_A16 (128 threads)
__device__ __forceinline__ void convert_slice(int s, const float4* __restrict__ embF, int tid) {
    const size_t base4 = ((size_t)s * 16 * DIMD) >> 2;
    const float4* src = embF + base4;
    uint2* dst = reinterpret_cast<uint2*>(g_A16) + base4;
    #pragma unroll 4
    for (int i = tid; i < 16 * DIMD / 4; i += 128) {
        const float4 v = src[i];
        __half2 h0 = __floats2half2_rn(v.x, v.y);
        __half2 h1 = __floats2half2_rn(v.z, v.w);
        dst[i] = make_uint2(*reinterpret_cast<const uint32_t*>(&h0),
                            *reinterpret_cast<const uint32_t*>(&h1));
    }
}

// ===================== phase 1: pure Sinkhorn (128 CTAs x 256 thr) =====================
__device__ __forceinline__ void grid_barrier_s(unsigned* tgt) {
    __syncthreads();
    if (threadIdx.x == 0) {
        __threadfence();
        atomicAdd(&g_bar, 1u);
        const unsigned t = *tgt;
        while (*((const volatile unsigned*)&g_bar) < t) { __nanosleep(32); }
        __threadfence();
    }
    __syncthreads();
    *tgt += NCTA_S;
}

__global__ void __launch_bounds__(STHR)
sinkhorn_kernel(const float* __restrict__ log_scores) {
    __shared__ float rows[RPC][DIMD];   // 32 KB
    __shared__ float cs_s[DIMD];        // 4 KB
    const int tid  = threadIdx.x;
    const int warp = tid >> 5;          // 8 warps = 8 rows
    const int lane = tid & 31;
    const int cta  = blockIdx.x;
    const int rbase = cta * RPC;

    // zero colSum + conversion flags (visibility covered by barrier 0 / kernel end)
    for (int i = cta * STHR + tid; i < NITERS * DIMD; i += NCTA_S * STHR)
        (&g_colSum[0][0])[i] = 0.f;
    for (int i = cta * STHR + tid; i < NSLICES; i += NCTA_S * STHR) {
        g_claim[i] = 0u;
        g_ready[i] = 0u;
    }

    // load rows, go to probability domain (TAU = 1)
    for (int i = tid; i < RPC * DIMD; i += STHR)
        rows[i >> 10][i & 1023] = __expf(log_scores[(size_t)rbase * DIMD + i]);

    unsigned tgt = NCTA_S;
    grid_barrier_s(&tgt);

    for (int iter = 0; iter < NITERS; ++iter) {
        if (iter > 0) {
            #pragma unroll
            for (int c = tid; c < DIMD; c += STHR)
                cs_s[c] = __frcp_rn(g_colSum[iter - 1][c]);
            __syncthreads();
        }

        // row normalize: warp w owns row w (fold pending column division)
        {
            float v[32];
            float s = 0.f;
            #pragma unroll
            for (int j = 0; j < 32; ++j) {
                const int col = lane + j * 32;
                float x = rows[warp][col];
                if (iter > 0) x *= cs_s[col];
                v[j] = x;
                s += x;
            }
            #pragma unroll
            for (int o = 16; o; o >>= 1) s += __shfl_xor_sync(0xFFFFFFFFu, s, o);
            const float inv = __frcp_rn(s);
            #pragma unroll
            for (int j = 0; j < 32; ++j) rows[warp][lane + j * 32] = v[j] * inv;
        }
        __syncthreads();

        // column partial over this CTA's 8 rows -> one atomic per column
        #pragma unroll
        for (int c = 0; c < DIMD / STHR; ++c) {
            const int col = tid + c * STHR;
            float p = 0.f;
            #pragma unroll
            for (int r = 0; r < RPC; ++r) p += rows[r][col];
            atomicAdd(&g_colSum[iter][col], p);
        }

        grid_barrier_s(&tgt);
    }

    // final: apply last column normalization, emit P as fp16 (K-major B operand)
    #pragma unroll
    for (int c = tid; c < DIMD; c += STHR)
        cs_s[c] = __frcp_rn(g_colSum[NITERS - 1][c]);
    __syncthreads();
    for (int i = tid; i < RPC * DIMD; i += STHR) {
        const int r = i >> 10, col = i & 1023;
        g_P[(size_t)(rbase + r) * DIMD + col] = __float2half(rows[r][col] * cs_s[col]);
    }

    // reset barrier counters for the next graph replay
    __syncthreads();
    if (tid == 0) {
        __threadfence();
        atomicAdd(&g_done, 1u);
        if (blockIdx.x == 0) {
            while (*((const volatile unsigned*)&g_done) < NCTA_S) { }
            g_bar = 0u;
            g_done = 0u;
            __threadfence();
        }
    }
}

// ===================== side-stream converter (runs concurrent with GEMM) =====================
__global__ void __launch_bounds__(128)
cvt_kernel(const float4* __restrict__ embF) {
    __shared__ unsigned won;
    const int tid = threadIdx.x;
    for (int s = blockIdx.x; s < NSLICES; s += CVT_CTAS) {
        if (tid == 0) won = (atomicExch(&g_claim[s], 1u) == 0u) ? 1u : 0u;
        __syncthreads();
        if (won) {
            convert_slice(s, embF, tid);
            __threadfence();
            __syncthreads();
            if (tid == 0) atomicExch(&g_ready[s], 1u);
        }
        __syncthreads();
    }
}

// ===================== GEMM: out = A16 @ P^T =====================
// CTA tile 128x128, 4 warps (2x2), warp tile 64x64, K-stage 64 (16 stages), 3-stage cp.async.
// Prologue: self-convert own slice iff unclaimed, then wait for the mtile's 8 slices.
#define KSTAGES 16
#define STAGE_BYTES 16384
#define B_BASE (3 * STAGE_BYTES)
#define GSMEM_BYTES (6 * STAGE_BYTES)

__global__ void __launch_bounds__(128, 2)
gemm_kernel(const float4* __restrict__ embF, float* __restrict__ out) {
    extern __shared__ __align__(1024) char smem[];
    const uint32_t sb = smem_to_u32(smem);
    const int tid  = threadIdx.x;
    const int wid  = tid >> 5;
    const int lane = tid & 31;

    // ntile fast-moving -> 8 consecutive CTAs share one A row-block (L2 reuse of A)
    const int ntile = blockIdx.x & 7;
    const int mtile = blockIdx.x >> 3;
    const int m0 = mtile * 128;
    const int n0 = ntile * 128;

    // ---- A-availability prologue ----
    {
        const int slice = blockIdx.x;          // == mtile*8 + ntile
        __shared__ unsigned won;
        if (tid == 0) won = (atomicExch(&g_claim[slice], 1u) == 0u) ? 1u : 0u;
        __syncthreads();
        if (won) {
            convert_slice(slice, embF, tid);
            __threadfence();
            __syncthreads();
            if (tid == 0) atomicExch(&g_ready[slice], 1u);
        }
        // wait for all 8 slices of this mtile
        if (tid < 8) {
            while (*((const volatile unsigned*)&g_ready[mtile * 8 + tid]) == 0u) { __nanosleep(32); }
        }
        __syncthreads();
        __threadfence();
    }

    const __half* Ag = g_A16 + (size_t)m0 * DIMD;
    const __half* Bg = g_P   + (size_t)n0 * DIMD;

#define ISSUE_STAGE(st, buf)                                                     \
    {                                                                            \
        const __half* asrc = Ag + (st) * 64;                                     \
        const __half* bsrc = Bg + (st) * 64;                                     \
        const uint32_t abase = sb + (buf) * STAGE_BYTES;                         \
        const uint32_t bbase = sb + B_BASE + (buf) * STAGE_BYTES;                \
        _Pragma("unroll")                                                        \
        for (int i = 0; i < 8; ++i) {                                            \
            const int idx = tid + i * 128;                                       \
            const int r = idx >> 3, c = idx & 7;                                 \
            const uint32_t sw = (uint32_t)(r * 128 + ((c * 16) ^ ((r & 7) << 4)));\
            CP_ASYNC16(abase + sw, asrc + (size_t)r * DIMD + c * 8);             \
            CP_ASYNC16(bbase + sw, bsrc + (size_t)r * DIMD + c * 8);             \
        }                                                                        \
        CP_ASYNC_COMMIT();                                                       \
    }

    const int warp_m = wid >> 1;   // 0..1
    const int warp_n = wid & 1;    // 0..1

    int a_pre[4], a_sw[4];
    {
        const int rr = ((lane >> 3) & 1) * 8 + (lane & 7);
        #pragma unroll
        for (int mt = 0; mt < 4; ++mt) {
            const int row = warp_m * 64 + mt * 16 + rr;
            a_pre[mt] = row * 128;
            a_sw[mt]  = (row & 7) << 4;
        }
    }
    const int a_k16 = ((lane >> 4) & 1) * 16;

    int b_pre[4], b_sw[4];
    {
        const int rr = ((lane >> 4) & 1) * 8 + (lane & 7);
        #pragma unroll
        for (int np = 0; np < 4; ++np) {
            const int row = warp_n * 64 + np * 16 + rr;
            b_pre[np] = row * 128;
            b_sw[np]  = (row & 7) << 4;
        }
    }
    const int b_k16 = ((lane >> 3) & 1) * 16;

    float acc[4][8][4];
    #pragma unroll
    for (int mt = 0; mt < 4; ++mt)
        #pragma unroll
        for (int nt = 0; nt < 8; ++nt)
            #pragma unroll
            for (int j = 0; j < 4; ++j) acc[mt][nt][j] = 0.f;

    ISSUE_STAGE(0, 0);
    ISSUE_STAGE(1, 1);

    for (int s = 0; s < KSTAGES; ++s) {
        const int buf = s % 3;
        CP_ASYNC_WAIT1();
        __syncthreads();
        if (s + 2 < KSTAGES) { ISSUE_STAGE(s + 2, (s + 2) % 3); }
        else                 { CP_ASYNC_COMMIT(); }

        const uint32_t Ab = sb + buf * STAGE_BYTES;
        const uint32_t Bb = sb + B_BASE + buf * STAGE_BYTES;
        #pragma unroll
        for (int ks = 0; ks < 4; ++ks) {
            const int kb = ks * 32;
            uint32_t av[4][4];
            #pragma unroll
            for (int mt = 0; mt < 4; ++mt)
                ldsm_x4(av[mt], Ab + a_pre[mt] + ((kb | a_k16) ^ a_sw[mt]));
            uint32_t bv[4][4];
            #pragma unroll
            for (int np = 0; np < 4; ++np)
                ldsm_x4(bv[np], Bb + b_pre[np] + ((kb | b_k16) ^ b_sw[np]));
            #pragma unroll
            for (int mt = 0; mt < 4; ++mt)
                #pragma unroll
                for (int np = 0; np < 4; ++np) {
                    mma16816(acc[mt][2 * np + 0], av[mt], bv[np][0], bv[np][1]);
                    mma16816(acc[mt][2 * np + 1], av[mt], bv[np][2], bv[np][3]);
                }
        }
    }
#undef ISSUE_STAGE

    // epilogue: direct coalesced STG.64
    const int r0c = lane >> 2;
    const int c0c = (lane & 3) * 2;
    #pragma unroll
    for (int mt = 0; mt < 4; ++mt) {
        const int row_base = m0 + warp_m * 64 + mt * 16 + r0c;
        #pragma unroll
        for (int nt = 0; nt < 8; ++nt) {
            const int col = n0 + warp_n * 64 + nt * 8 + c0c;
            float2 v0 = make_float2(acc[mt][nt][0], acc[mt][nt][1]);
            float2 v1 = make_float2(acc[mt][nt][2], acc[mt][nt][3]);
            *reinterpret_cast<float2*>(out + (size_t)row_base * DIMD + col)       = v0;
            *reinterpret_cast<float2*>(out + (size_t)(row_base + 8) * DIMD + col) = v1;
        }
    }
}

// ===================== launch =====================
extern "C" void kernel_launch(void* const* d_in, const int* in_sizes, int n_in,
                              void* d_out, int out_size) {
    const float* emb;
    const float* ls;
    if (n_in >= 2 && in_sizes[0] == DIMD * DIMD && in_sizes[1] != DIMD * DIMD) {
        ls  = (const float*)d_in[0];
        emb = (const float*)d_in[1];
    } else {
        emb = (const float*)d_in[0];
        ls  = (const float*)d_in[1];
    }
    float* out = (float*)d_out;
    const float4* embF = reinterpret_cast<const float4*>(emb);

    static cudaStream_t s2 = nullptr;
    static cudaEvent_t eS = nullptr, eC = nullptr;
    if (s2 == nullptr) {
        cudaStreamCreateWithFlags(&s2, cudaStreamNonBlocking);
        cudaEventCreateWithFlags(&eS, cudaEventDisableTiming);
        cudaEventCreateWithFlags(&eC, cudaEventDisableTiming);
        cudaFuncSetAttribute(gemm_kernel, cudaFuncAttributeMaxDynamicSharedMemorySize, GSMEM_BYTES);
    }

    // stream 0:  sinkhorn ───────────────► gemm ──► (join)
    // stream s2:          └► cvt (concurrent with gemm) ┘
    sinkhorn_kernel<<<NCTA_S, STHR>>>(ls);
    cudaEventRecord(eS, 0);
    cudaStreamWaitEvent(s2, eS, 0);
    cvt_kernel<<<CVT_CTAS, 128, 0, s2>>>(embF);
    cudaEventRecord(eC, s2);
    gemm_kernel<<<(BATCH / 128) * (DIMD / 128), 128, GSMEM_BYTES>>>(embF, out);
    cudaStreamWaitEvent(0, eC, 0);
}